// round 10
// baseline (speedup 1.0000x reference)
#include <cuda_runtime.h>
#include <stdint.h>

// Problem dims
#define B_  2
#define S_  2048
#define D_  1024
#define H_  16
#define HD_ 64
#define BS_ (B_ * S_)         // 4096
#define NX  (BS_ * D_)
#define NW  (H_ * D_ * HD_)

// tf32-bit scratch (device globals — allocation-guard safe)
__device__ uint32_t g_xt[NX];
__device__ uint32_t g_wqt[NW], g_wkt[NW], g_wvt[NW], g_wot[D_ * D_];
__device__ float    g_bqs[H_ * HD_];
__device__ uint32_t g_q[B_ * H_ * S_ * HD_];   // pre-scaled by 1/8
__device__ uint32_t g_k[B_ * H_ * S_ * HD_];
__device__ uint32_t g_v[B_ * H_ * S_ * HD_];
__device__ uint32_t g_wv[BS_ * D_];            // [B,S,H*HD] tf32 bits

__device__ __forceinline__ uint32_t f2tf(float f) {
    uint32_t u;
    asm("cvt.rna.tf32.f32 %0, %1;" : "=r"(u) : "f"(f));
    return u;
}

__device__ __forceinline__ void mma_tf32(float c[4], const uint32_t a[4],
                                         uint32_t b0, uint32_t b1) {
    asm volatile(
        "mma.sync.aligned.m16n8k8.row.col.f32.tf32.tf32.f32 "
        "{%0,%1,%2,%3}, {%4,%5,%6,%7}, {%8,%9}, {%0,%1,%2,%3};"
        : "+f"(c[0]), "+f"(c[1]), "+f"(c[2]), "+f"(c[3])
        : "r"(a[0]), "r"(a[1]), "r"(a[2]), "r"(a[3]), "r"(b0), "r"(b1));
}

__device__ __forceinline__ void ldm4(uint32_t r[4], uint32_t addr) {
    asm volatile("ldmatrix.sync.aligned.m8n8.x4.shared.b16 {%0,%1,%2,%3}, [%4];"
        : "=r"(r[0]), "=r"(r[1]), "=r"(r[2]), "=r"(r[3]) : "r"(addr));
}

#define CP16(d, s)  asm volatile("cp.async.cg.shared.global [%0], [%1], 16;" :: "r"(d), "l"(s))
#define CPCOMMIT()  asm volatile("cp.async.commit_group;")
#define CPWAIT(n)   asm volatile("cp.async.wait_group %0;" :: "n"(n))

// ---------------------------------------------------------------------------
// Convert: tf32-round x and weights (fold 1/8 scale into Wq, bq)
// ---------------------------------------------------------------------------
__global__ __launch_bounds__(256) void convert_kernel(
    const float* __restrict__ x,  const float* __restrict__ Wq,
    const float* __restrict__ bq, const float* __restrict__ Wk,
    const float* __restrict__ Wv, const float* __restrict__ Wo)
{
    long long i = (long long)blockIdx.x * 256 + threadIdx.x;
    if (i < NX) { g_xt[i] = f2tf(x[i]); return; }
    i -= NX;
    if (i < NW) { g_wqt[i] = f2tf(Wq[i] * 0.125f); return; }
    i -= NW;
    if (i < NW) { g_wkt[i] = f2tf(Wk[i]); return; }
    i -= NW;
    if (i < NW) { g_wvt[i] = f2tf(Wv[i]); return; }
    i -= NW;
    if (i < D_ * D_) { g_wot[i] = f2tf(Wo[i]); return; }
    i -= D_ * D_;
    if (i < H_ * HD_) { g_bqs[i] = bq[i] * 0.125f; }
}

// ---------------------------------------------------------------------------
// QKV projection: 512 threads, tile 128(M) x 256(N = 4 heads) x 32(K).
// 16 warps as 4x4, warp tile 32x64. 3-buffer ring (prefill 2, issue c+2).
// sA [row][k] stride 36; sB [k][n] stride 264 (banks 8k+n: conflict-free).
// grid (32, 4, 3).
// ---------------------------------------------------------------------------
#define QA_ST 36
#define QAW   (128 * QA_ST)      // 4608 words
#define QB_ST 264
#define QBW   (32 * QB_ST)       // 8448 words
#define QSTG  (QAW + QBW)        // 13056 words/stage
#define QKV_SMEM (3 * QSTG * 4)  // 156672 bytes

__global__ __launch_bounds__(512, 1) void qkv_kernel(
    const float* __restrict__ bk, const float* __restrict__ bv)
{
    extern __shared__ uint32_t dsm[];
    const int rt = blockIdx.x, hp = blockIdx.y, m = blockIdx.z;
    const uint32_t* W    = (m == 0) ? g_wqt : (m == 1) ? g_wkt : g_wvt;
    const float*    bias = (m == 0) ? g_bqs : (m == 1) ? bk : bv;
    uint32_t*       out  = (m == 0) ? g_q : (m == 1) ? g_k : g_v;

    const int tid  = threadIdx.x;
    const int wid  = tid >> 5;
    const int lane = tid & 31;
    const int wm   = wid >> 2, wn = wid & 3;   // 4x4 warp grid
    const int ql   = lane & 3, qr = lane >> 2;
    const int row0 = rt * 128;
    const int h0   = hp * 4;                   // 4 heads per block

    const uint32_t sm0 = (uint32_t)__cvta_generic_to_shared(dsm);
    const uint32_t aLane = ((wm * 32 + (lane & 15)) * QA_ST + (lane >> 4) * 4) * 4;

    float acc[2][8][4];
    #pragma unroll
    for (int mi = 0; mi < 2; mi++)
        #pragma unroll
        for (int ni = 0; ni < 8; ni++)
            #pragma unroll
            for (int c = 0; c < 4; c++) acc[mi][ni][c] = 0.f;

    #define QKV_STAGE(c, s) {                                                  \
        uint32_t sb = sm0 + (s) * QSTG * 4;                                    \
        _Pragma("unroll")                                                      \
        for (int i = 0; i < 2; i++) {                                          \
            int g = i * 512 + tid; int row = g >> 3; int kg = (g & 7) * 4;     \
            CP16(sb + (row * QA_ST + kg) * 4,                                  \
                 &g_xt[(size_t)(row0 + row) * D_ + (c) * 32 + kg]);            \
        }                                                                      \
        _Pragma("unroll")                                                      \
        for (int i = 0; i < 4; i++) {                                          \
            int g = i * 512 + tid; int k = g >> 6; int n0 = g & 63;            \
            CP16(sb + (QAW + k * QB_ST + n0 * 4) * 4,                          \
                 &W[((size_t)(h0 + (n0 >> 4)) * D_ + (c) * 32 + k) * HD_ + (n0 & 15) * 4]); \
        }                                                                      \
    }

    QKV_STAGE(0, 0); CPCOMMIT();
    QKV_STAGE(1, 1); CPCOMMIT();

    for (int c = 0; c < 32; c++) {
        const int cur = c % 3;
        CPWAIT(1);                       // stage c landed
        __syncthreads();                 // everyone done with compute c-1
        if (c + 2 < 32) { QKV_STAGE(c + 2, (c + 2) % 3); }
        CPCOMMIT();

        const uint32_t sAb = sm0 + cur * QSTG * 4;
        const uint32_t* sB = dsm + cur * QSTG + QAW;

        #pragma unroll
        for (int kk = 0; kk < 4; kk++) {
            uint32_t a[2][4];
            #pragma unroll
            for (int mi = 0; mi < 2; mi++)
                ldm4(a[mi], sAb + aLane + (mi * 16 * QA_ST + kk * 8) * 4);
            uint32_t b0[8], b1[8];
            #pragma unroll
            for (int ni = 0; ni < 8; ni++) {
                int n = wn * 64 + ni * 8 + qr;
                b0[ni] = sB[(kk * 8 + ql) * QB_ST + n];
                b1[ni] = sB[(kk * 8 + ql + 4) * QB_ST + n];
            }
            #pragma unroll
            for (int mi = 0; mi < 2; mi++)
                #pragma unroll
                for (int ni = 0; ni < 8; ni++)
                    mma_tf32(acc[mi][ni], a[mi], b0[ni], b1[ni]);
        }
    }

    // epilogue: tf32 bits, layout [B,H,S,HD]
    #pragma unroll
    for (int mi = 0; mi < 2; mi++) {
        int row = row0 + wm * 32 + mi * 16 + qr;
        int bb  = row >> 11;
        int s   = row & (S_ - 1);
        #pragma unroll
        for (int ni = 0; ni < 8; ni++) {
            int cl = wn * 64 + ni * 8 + 2 * ql;
            int h  = h0 + (cl >> 6);
            int e  = cl & 63;
            float bv0 = bias[h * HD_ + e];
            float bv1 = bias[h * HD_ + e + 1];
            uint32_t* p0 = out + (((size_t)bb * H_ + h) * S_ + s) * HD_ + e;
            uint32_t* p1 = out + (((size_t)bb * H_ + h) * S_ + s + 8) * HD_ + e;
            p0[0] = f2tf(acc[mi][ni][0] + bv0); p0[1] = f2tf(acc[mi][ni][1] + bv1);
            p1[0] = f2tf(acc[mi][ni][2] + bv0); p1[1] = f2tf(acc[mi][ni][3] + bv1);
        }
    }
}

// ---------------------------------------------------------------------------
// Flash attention (causal): 128 queries/block, 8 warps x 16 rows.
// Double-buffered K/V (issue kt+1 after barrier into freed buffer),
// warp-local P buffer, per-warp skip of fully masked tiles.
// grid (16 reversed, 32), 256 threads.
// ---------------------------------------------------------------------------
#define AK_W 4352                // 64*68
#define AV_W 4608                // 64*72
#define AP_OFF (2 * AK_W + 2 * AV_W)   // 17920
#define AP_W  (128 * 68)               // 8704
#define ATT_SMEM ((AP_OFF + AP_W) * 4) // 106496 bytes

__global__ __launch_bounds__(256, 1) void attn_kernel()
{
    extern __shared__ uint32_t dsm[];
    uint32_t* sV = dsm + 2 * AK_W;
    uint32_t* sP = dsm + AP_OFF;

    const int qt = 15 - blockIdx.x;      // 128-query tiles, big first
    const int bh = blockIdx.y;
    const int b  = bh >> 4;
    const int h  = bh & 15;
    const int tid  = threadIdx.x;
    const int w    = tid >> 5;           // 0..7
    const int lane = tid & 31;
    const int qr   = lane >> 2;
    const int ql   = lane & 3;

    const uint32_t* Qb = g_q + (size_t)bh * S_ * HD_;
    const uint32_t* Kb = g_k + (size_t)bh * S_ * HD_;
    const uint32_t* Vb = g_v + (size_t)bh * S_ * HD_;

    const uint32_t sk_b = (uint32_t)__cvta_generic_to_shared(dsm);
    const uint32_t sp_b = sk_b + AP_OFF * 4;
    const uint32_t aoff = ((w * 16 + (lane & 15)) * 68 + (lane >> 4) * 4) * 4;
    const uint32_t koff = ((lane & 15) * 68 + (lane >> 4) * 4) * 4;

    // ---- stage Q (pre-scaled) into sP, extract A fragments ----
    #pragma unroll
    for (int i = 0; i < 8; i++) {
        int g = i * 256 + tid;           // 0..2047 float4 units
        int row = g >> 4, c4 = (g & 15) * 4;
        CP16(sp_b + (row * 68 + c4) * 4, &Qb[(size_t)(qt * 128 + row) * HD_ + c4]);
    }
    CPCOMMIT(); CPWAIT(0);
    __syncthreads();

    uint32_t qa[8][4];
    #pragma unroll
    for (int kk = 0; kk < 8; kk++) ldm4(qa[kk], sp_b + aoff + kk * 32);
    __syncthreads();                     // Q frags extracted before P reuse

    #define ATT_STAGE(kt, s) {                                                 \
        _Pragma("unroll")                                                      \
        for (int i = 0; i < 4; i++) {                                          \
            int g = i * 256 + tid;                                             \
            int row = g >> 4, c4 = (g & 15) * 4;                               \
            CP16(sk_b + ((s) * AK_W + row * 68 + c4) * 4,                      \
                 &Kb[(size_t)((kt) * 64 + row) * HD_ + c4]);                   \
            CP16(sk_b + ((2 * AK_W + (s) * AV_W + row * 72 + c4)) * 4,         \
                 &Vb[(size_t)((kt) * 64 + row) * HD_ + c4]);                   \
        }                                                                      \
    }

    ATT_STAGE(0, 0); CPCOMMIT();

    float O[8][4];
    #pragma unroll
    for (int n = 0; n < 8; n++)
        #pragma unroll
        for (int c = 0; c < 4; c++) O[n][c] = 0.f;
    float m0 = -1e30f, m1 = -1e30f, l0 = 0.f, l1 = 0.f;

    const int rbase = qt * 128 + w * 16; // warp's first query row (global)
    const int nkt = 2 * qt + 2;

    for (int kt = 0; kt < nkt; kt++) {
        const int buf = kt & 1;
        CPWAIT(0);                       // tile kt landed
        __syncthreads();                 // all done with tile kt-1
        if (kt + 1 < nkt) { ATT_STAGE(kt + 1, buf ^ 1); }
        CPCOMMIT();

        if (kt * 64 > rbase + 15) continue;   // fully masked for this warp

        // ---- QK^T ----
        const uint32_t kbase = sk_b + buf * AK_W * 4;
        float sc[8][4];
        #pragma unroll
        for (int n = 0; n < 8; n++)
            #pragma unroll
            for (int c = 0; c < 4; c++) sc[n][c] = 0.f;
        #pragma unroll
        for (int kk = 0; kk < 8; kk++) {
            #pragma unroll
            for (int j = 0; j < 4; j++) {
                uint32_t kb[4];
                ldm4(kb, kbase + koff + (j * 16 * 68) * 4 + kk * 32);
                mma_tf32(sc[2 * j],     qa[kk], kb[0], kb[2]);
                mma_tf32(sc[2 * j + 1], qa[kk], kb[1], kb[3]);
            }
        }

        if (kt * 64 + 63 > rbase) {      // partial mask
            const int r0 = rbase + qr;   // global query rows r0, r0+8
            const int c0 = kt * 64;
            #pragma unroll
            for (int n = 0; n < 8; n++) {
                int cg = c0 + n * 8 + 2 * ql;
                if (cg     > r0)     sc[n][0] = -1e30f;
                if (cg + 1 > r0)     sc[n][1] = -1e30f;
                if (cg     > r0 + 8) sc[n][2] = -1e30f;
                if (cg + 1 > r0 + 8) sc[n][3] = -1e30f;
            }
        }

        // ---- online softmax ----
        float mt0 = -1e30f, mt1 = -1e30f;
        #pragma unroll
        for (int n = 0; n < 8; n++) {
            mt0 = fmaxf(mt0, fmaxf(sc[n][0], sc[n][1]));
            mt1 = fmaxf(mt1, fmaxf(sc[n][2], sc[n][3]));
        }
        mt0 = fmaxf(mt0, __shfl_xor_sync(0xffffffffu, mt0, 1));
        mt0 = fmaxf(mt0, __shfl_xor_sync(0xffffffffu, mt0, 2));
        mt1 = fmaxf(mt1, __shfl_xor_sync(0xffffffffu, mt1, 1));
        mt1 = fmaxf(mt1, __shfl_xor_sync(0xffffffffu, mt1, 2));
        float mn0 = fmaxf(m0, mt0), mn1 = fmaxf(m1, mt1);
        float cr0 = __expf(m0 - mn0), cr1 = __expf(m1 - mn1);
        m0 = mn0; m1 = mn1;
        #pragma unroll
        for (int n = 0; n < 8; n++) {
            O[n][0] *= cr0; O[n][1] *= cr0;
            O[n][2] *= cr1; O[n][3] *= cr1;
        }
        float s0 = 0.f, s1 = 0.f;
        #pragma unroll
        for (int n = 0; n < 8; n++) {
            sc[n][0] = __expf(sc[n][0] - mn0);
            sc[n][1] = __expf(sc[n][1] - mn0);
            sc[n][2] = __expf(sc[n][2] - mn1);
            sc[n][3] = __expf(sc[n][3] - mn1);
            s0 += sc[n][0] + sc[n][1];
            s1 += sc[n][2] + sc[n][3];
        }
        s0 += __shfl_xor_sync(0xffffffffu, s0, 1);
        s0 += __shfl_xor_sync(0xffffffffu, s0, 2);
        s1 += __shfl_xor_sync(0xffffffffu, s1, 1);
        s1 += __shfl_xor_sync(0xffffffffu, s1, 2);
        l0 = l0 * cr0 + s0;
        l1 = l1 * cr1 + s1;

        // ---- P (warp-local rows only) ----
        #pragma unroll
        for (int n = 0; n < 8; n++) {
            int cc = n * 8 + 2 * ql;
            uint32_t* d0 = &sP[(w * 16 + qr) * 68 + cc];
            uint32_t* d1 = &sP[(w * 16 + qr + 8) * 68 + cc];
            d0[0] = __float_as_uint(sc[n][0]); d0[1] = __float_as_uint(sc[n][1]);
            d1[0] = __float_as_uint(sc[n][2]); d1[1] = __float_as_uint(sc[n][3]);
        }
        __syncwarp();

        // ---- P @ V ----
        const uint32_t* sVb = sV + buf * AV_W;
        #pragma unroll
        for (int kk = 0; kk < 8; kk++) {
            uint32_t pa[4];
            ldm4(pa, sp_b + aoff + kk * 32);
            #pragma unroll
            for (int n = 0; n < 8; n++) {
                uint32_t vb0 = sVb[(kk * 8 + ql) * 72 + n * 8 + qr];
                uint32_t vb1 = sVb[(kk * 8 + ql + 4) * 72 + n * 8 + qr];
                mma_tf32(O[n], pa, vb0, vb1);
            }
        }
    }

    // ---- normalize + store tf32 bits to g_wv [B,S,H*HD] ----
    float inv0 = 1.f / l0, inv1 = 1.f / l1;
    int r0g = qt * 128 + w * 16 + qr;
    uint32_t* base0 = g_wv + ((size_t)b * S_ + r0g) * D_ + h * HD_;
    uint32_t* base1 = g_wv + ((size_t)b * S_ + r0g + 8) * D_ + h * HD_;
    #pragma unroll
    for (int n = 0; n < 8; n++) {
        int cc = n * 8 + 2 * ql;
        base0[cc]     = f2tf(O[n][0] * inv0);
        base0[cc + 1] = f2tf(O[n][1] * inv0);
        base1[cc]     = f2tf(O[n][2] * inv1);
        base1[cc + 1] = f2tf(O[n][3] * inv1);
    }
}

// ---------------------------------------------------------------------------
// Output projection: 512 threads, tile 128 x 256, 3-buffer ring, ldmatrix A+B.
// grid (32, 4) = 128 blocks (single wave).
// ---------------------------------------------------------------------------
#define OA_ST 36
#define OAW   (128 * OA_ST)     // 4608 words (A)
#define OBW   (256 * OA_ST)     // 9216 words (B)
#define OSTG  (OAW + OBW)       // 13824 words/stage
#define OP_SMEM (3 * OSTG * 4)  // 165888 bytes

__global__ __launch_bounds__(512, 1) void oproj_kernel(
    const float* __restrict__ bo, float* __restrict__ out)
{
    extern __shared__ uint32_t dsm[];
    const int rt = blockIdx.x, ct = blockIdx.y;

    const int tid  = threadIdx.x;
    const int wid  = tid >> 5;
    const int lane = tid & 31;
    const int wm   = wid >> 2, wn = wid & 3;
    const int ql   = lane & 3, qr = lane >> 2;
    const int row0 = rt * 128;
    const int col0 = ct * 256;

    const uint32_t sm0 = (uint32_t)__cvta_generic_to_shared(dsm);
    const uint32_t aLane = ((wm * 32 + (lane & 15)) * OA_ST + (lane >> 4) * 4) * 4;
    const uint32_t bLane = ((wn * 64 + (lane & 15)) * OA_ST + (lane >> 4) * 4) * 4;

    float acc[2][8][4];
    #pragma unroll
    for (int mi = 0; mi < 2; mi++)
        #pragma unroll
        for (int ni = 0; ni < 8; ni++)
            #pragma unroll
            for (int c = 0; c < 4; c++) acc[mi][ni][c] = 0.f;

    #define OP_STAGE(c, s) {                                                   \
        uint32_t sb = sm0 + (s) * OSTG * 4;                                    \
        _Pragma("unroll")                                                      \
        for (int i = 0; i < 2; i++) {                                          \
            int g = i * 512 + tid; int row = g >> 3; int kg = (g & 7) * 4;     \
            CP16(sb + (row * OA_ST + kg) * 4,                                  \
                 &g_wv[(size_t)(row0 + row) * D_ + (c) * 32 + kg]);            \
        }                                                                      \
        _Pragma("unroll")                                                      \
        for (int i = 0; i < 4; i++) {                                          \
            int g = i * 512 + tid; int n = g >> 3; int kg = (g & 7) * 4;       \
            CP16(sb + (OAW + n * OA_ST + kg) * 4,                              \
                 &g_wot[(size_t)(col0 + n) * D_ + (c) * 32 + kg]);             \
        }                                                                      \
    }

    OP_STAGE(0, 0); CPCOMMIT();
    OP_STAGE(1, 1); CPCOMMIT();

    for (int c = 0; c < 32; c++) {
        const int cur = c % 3;
        CPWAIT(1);
        __syncthreads();
        if (c + 2 < 32) { OP_STAGE(c + 2, (c + 2) % 3); }
        CPCOMMIT();

        const uint32_t sAb = sm0 + cur * OSTG * 4;
        const uint32_t sBb = sAb + OAW * 4;

        #pragma unroll
        for (int kk = 0; kk < 4; kk++) {
            uint32_t a[2][4];
            #pragma unroll
            for (int mi = 0; mi < 2; mi++)
                ldm4(a[mi], sAb + aLane + (mi * 16 * OA_ST + kk * 8) * 4);
            uint32_t bb[4][4];
            #pragma unroll
            for (int nj = 0; nj < 4; nj++)
                ldm4(bb[nj], sBb + bLane + (nj * 16 * OA_ST + kk * 8) * 4);
            #pragma unroll
            for (int mi = 0; mi < 2; mi++)
                #pragma unroll
                for (int nj = 0; nj < 4; nj++) {
                    mma_tf32(acc[mi][2 * nj],     a[mi], bb[nj][0], bb[nj][2]);
                    mma_tf32(acc[mi][2 * nj + 1], a[mi], bb[nj][1], bb[nj][3]);
                }
        }
    }

    #pragma unroll
    for (int mi = 0; mi < 2; mi++) {
        int row = row0 + wm * 32 + mi * 16 + qr;
        #pragma unroll
        for (int ni = 0; ni < 8; ni++) {
            int col = col0 + wn * 64 + ni * 8 + 2 * ql;
            float bv0 = bo[col], bv1 = bo[col + 1];
            *(float2*)&out[(size_t)row * D_ + col] =
                make_float2(acc[mi][ni][0] + bv0, acc[mi][ni][1] + bv1);
            *(float2*)&out[(size_t)(row + 8) * D_ + col] =
                make_float2(acc[mi][ni][2] + bv0, acc[mi][ni][3] + bv1);
        }
    }
}

// ---------------------------------------------------------------------------
// Launch. metadata order: x, Wq, bq, Wk, bk, Wv, bv, Wo, bo
// ---------------------------------------------------------------------------
extern "C" void kernel_launch(void* const* d_in, const int* in_sizes, int n_in,
                              void* d_out, int out_size)
{
    const float* x  = (const float*)d_in[0];
    const float* Wq = (const float*)d_in[1];
    const float* bq = (const float*)d_in[2];
    const float* Wk = (const float*)d_in[3];
    const float* bk = (const float*)d_in[4];
    const float* Wv = (const float*)d_in[5];
    const float* bv = (const float*)d_in[6];
    const float* Wo = (const float*)d_in[7];
    const float* bo = (const float*)d_in[8];
    float* out = (float*)d_out;

    cudaFuncSetAttribute(qkv_kernel,   cudaFuncAttributeMaxDynamicSharedMemorySize, QKV_SMEM);
    cudaFuncSetAttribute(attn_kernel,  cudaFuncAttributeMaxDynamicSharedMemorySize, ATT_SMEM);
    cudaFuncSetAttribute(oproj_kernel, cudaFuncAttributeMaxDynamicSharedMemorySize, OP_SMEM);

    const long long ntot = (long long)NX + 4LL * NW + H_ * HD_;
    convert_kernel<<<(int)((ntot + 255) / 256), 256>>>(x, Wq, bq, Wk, Wv, Wo);

    dim3 g1(BS_ / 128, H_ / 4, 3);
    qkv_kernel<<<g1, 512, QKV_SMEM>>>(bk, bv);

    dim3 g2(S_ / 128, B_ * H_);
    attn_kernel<<<g2, 256, ATT_SMEM>>>();

    dim3 g3(BS_ / 128, D_ / 256);
    oproj_kernel<<<g3, 512, OP_SMEM>>>(bo, out);
}

// round 12
// speedup vs baseline: 1.8032x; 1.8032x over previous
#include <cuda_runtime.h>
#include <cuda_fp16.h>
#include <stdint.h>

// Problem dims
#define B_  2
#define S_  2048
#define D_  1024
#define H_  16
#define HD_ 64
#define BS_ (B_ * S_)         // 4096
#define NX  (BS_ * D_)
#define NW  (H_ * D_ * HD_)

// fp16 scratch (device globals — allocation-guard safe)
__device__ __align__(16) __half g_xh[NX];
__device__ __align__(16) __half g_wqh[NW], g_wkh[NW], g_wvh[NW], g_woh[D_ * D_];
__device__ float g_bqs[H_ * HD_];
__device__ __align__(16) __half g_q[B_ * H_ * S_ * HD_];   // pre-scaled by 1/8
__device__ __align__(16) __half g_k[B_ * H_ * S_ * HD_];
__device__ __align__(16) __half g_v[B_ * H_ * S_ * HD_];
__device__ __align__(16) __half g_wv[BS_ * D_];            // [B,S,H*HD]

__device__ __forceinline__ void mma_f16(float c[4], const uint32_t a[4],
                                        uint32_t b0, uint32_t b1) {
    asm volatile(
        "mma.sync.aligned.m16n8k16.row.col.f32.f16.f16.f32 "
        "{%0,%1,%2,%3}, {%4,%5,%6,%7}, {%8,%9}, {%0,%1,%2,%3};"
        : "+f"(c[0]), "+f"(c[1]), "+f"(c[2]), "+f"(c[3])
        : "r"(a[0]), "r"(a[1]), "r"(a[2]), "r"(a[3]), "r"(b0), "r"(b1));
}

__device__ __forceinline__ void ldm4(uint32_t r[4], uint32_t addr) {
    asm volatile("ldmatrix.sync.aligned.m8n8.x4.shared.b16 {%0,%1,%2,%3}, [%4];"
        : "=r"(r[0]), "=r"(r[1]), "=r"(r[2]), "=r"(r[3]) : "r"(addr));
}
__device__ __forceinline__ void ldm4t(uint32_t r[4], uint32_t addr) {
    asm volatile("ldmatrix.sync.aligned.m8n8.x4.trans.shared.b16 {%0,%1,%2,%3}, [%4];"
        : "=r"(r[0]), "=r"(r[1]), "=r"(r[2]), "=r"(r[3]) : "r"(addr));
}

#define CP16(d, s)  asm volatile("cp.async.cg.shared.global [%0], [%1], 16;" :: "r"(d), "l"(s))
#define CPCOMMIT()  asm volatile("cp.async.commit_group;")
#define CPWAIT(n)   asm volatile("cp.async.wait_group %0;" :: "n"(n))

// ---------------------------------------------------------------------------
// Convert to fp16 (fold 1/8 attention scale into Wq, bq)
// ---------------------------------------------------------------------------
__global__ __launch_bounds__(256) void convert_kernel(
    const float* __restrict__ x,  const float* __restrict__ Wq,
    const float* __restrict__ bq, const float* __restrict__ Wk,
    const float* __restrict__ Wv, const float* __restrict__ Wo)
{
    long long i = (long long)blockIdx.x * 256 + threadIdx.x;
    if (i < NX) { g_xh[i] = __float2half_rn(x[i]); return; }
    i -= NX;
    if (i < NW) { g_wqh[i] = __float2half_rn(Wq[i] * 0.125f); return; }
    i -= NW;
    if (i < NW) { g_wkh[i] = __float2half_rn(Wk[i]); return; }
    i -= NW;
    if (i < NW) { g_wvh[i] = __float2half_rn(Wv[i]); return; }
    i -= NW;
    if (i < D_ * D_) { g_woh[i] = __float2half_rn(Wo[i]); return; }
    i -= D_ * D_;
    if (i < H_ * HD_) { g_bqs[i] = bq[i] * 0.125f; }
}

// ---------------------------------------------------------------------------
// QKV projection (fp16): 512 threads, tile 128(M) x 256(N=4 heads) x 32(K).
// 16 warps 4x4, warp tile 32x64. 3-buffer ring (prefill 2, issue c+2).
// sA [row][k] stride 40 halves; sB [k][n] stride 264 halves (trans ldmatrix).
// grid (32, 4, 3).
// ---------------------------------------------------------------------------
#define QA_ST 40
#define QAW   (128 * QA_ST)       // 5120 halves
#define QB_ST 264
#define QBW   (32 * QB_ST)        // 8448 halves
#define QSTG  (QAW + QBW)         // 13568 halves/stage
#define QKV_SMEM (3 * QSTG * 2)   // 81408 bytes

__global__ __launch_bounds__(512, 1) void qkv_kernel(
    const float* __restrict__ bk, const float* __restrict__ bv)
{
    extern __shared__ __half hsm[];
    const int rt = blockIdx.x, hp = blockIdx.y, m = blockIdx.z;
    const __half* W    = (m == 0) ? g_wqh : (m == 1) ? g_wkh : g_wvh;
    const float*  bias = (m == 0) ? g_bqs : (m == 1) ? bk : bv;
    __half*       out  = (m == 0) ? g_q : (m == 1) ? g_k : g_v;

    const int tid  = threadIdx.x;
    const int wid  = tid >> 5;
    const int lane = tid & 31;
    const int wm   = wid >> 2, wn = wid & 3;
    const int ql   = lane & 3, qr = lane >> 2;
    const int row0 = rt * 128;
    const int h0   = hp * 4;

    const uint32_t sm0 = (uint32_t)__cvta_generic_to_shared(hsm);
    // A-frag (non-trans): 16 rows (lane&15), 16B col select (lane>>4)
    const uint32_t aLane = ((wm * 32 + (lane & 15)) * QA_ST) * 2 + (lane >> 4) * 16;
    // B-frag (trans): k-row (lane&7)+((lane>>3)&1)*8, n col (lane>>4)*8
    const int klane = (lane & 7) + ((lane >> 3) & 1) * 8;
    const uint32_t bLane = (klane * QB_ST + (lane >> 4) * 8 + wn * 64) * 2;

    float acc[2][8][4];
    #pragma unroll
    for (int mi = 0; mi < 2; mi++)
        #pragma unroll
        for (int ni = 0; ni < 8; ni++)
            #pragma unroll
            for (int c = 0; c < 4; c++) acc[mi][ni][c] = 0.f;

    #define QKV_STAGE(c, s) {                                                  \
        uint32_t sb = sm0 + (s) * QSTG * 2;                                    \
        {   /* A: 128 rows x 32 halves = 512 CP16 */                           \
            int g = tid; int row = g >> 2; int kg = (g & 3) * 8;               \
            CP16(sb + (row * QA_ST + kg) * 2,                                  \
                 &g_xh[(size_t)(row0 + row) * D_ + (c) * 32 + kg]);            \
        }                                                                      \
        _Pragma("unroll")                                                      \
        for (int i = 0; i < 2; i++) {  /* B: [k][n] 32x256 = 1024 CP16 */      \
            int g = i * 512 + tid; int k = g >> 5; int n8 = (g & 31) * 8;      \
            CP16(sb + (QAW + k * QB_ST + n8) * 2,                              \
                 &W[((size_t)(h0 + (n8 >> 6)) * D_ + (c) * 32 + k) * HD_ + (n8 & 63)]); \
        }                                                                      \
    }

    QKV_STAGE(0, 0); CPCOMMIT();
    QKV_STAGE(1, 1); CPCOMMIT();

    for (int c = 0; c < 32; c++) {
        const int cur = c % 3;
        CPWAIT(1);
        __syncthreads();
        if (c + 2 < 32) { QKV_STAGE(c + 2, (c + 2) % 3); }
        CPCOMMIT();

        const uint32_t sAb = sm0 + cur * QSTG * 2;
        const uint32_t sBb = sAb + QAW * 2;

        #pragma unroll
        for (int kk = 0; kk < 2; kk++) {
            uint32_t a[2][4];
            #pragma unroll
            for (int mi = 0; mi < 2; mi++)
                ldm4(a[mi], sAb + aLane + mi * 16 * QA_ST * 2 + kk * 32);
            uint32_t bb[4][4];
            #pragma unroll
            for (int nj = 0; nj < 4; nj++)
                ldm4t(bb[nj], sBb + bLane + (kk * 16 * QB_ST + nj * 16) * 2);
            #pragma unroll
            for (int mi = 0; mi < 2; mi++)
                #pragma unroll
                for (int nj = 0; nj < 4; nj++) {
                    mma_f16(acc[mi][2 * nj],     a[mi], bb[nj][0], bb[nj][1]);
                    mma_f16(acc[mi][2 * nj + 1], a[mi], bb[nj][2], bb[nj][3]);
                }
        }
    }

    // epilogue: fp16, layout [B,H,S,HD]
    #pragma unroll
    for (int mi = 0; mi < 2; mi++) {
        int row = row0 + wm * 32 + mi * 16 + qr;
        int bb  = row >> 11;
        int s   = row & (S_ - 1);
        #pragma unroll
        for (int ni = 0; ni < 8; ni++) {
            int cl = wn * 64 + ni * 8 + 2 * ql;
            int h  = h0 + (cl >> 6);
            int e  = cl & 63;
            float bv0 = bias[h * HD_ + e];
            float bv1 = bias[h * HD_ + e + 1];
            __half* p0 = out + (((size_t)bb * H_ + h) * S_ + s) * HD_ + e;
            __half* p1 = out + (((size_t)bb * H_ + h) * S_ + s + 8) * HD_ + e;
            *(__half2*)p0 = __floats2half2_rn(acc[mi][ni][0] + bv0, acc[mi][ni][1] + bv1);
            *(__half2*)p1 = __floats2half2_rn(acc[mi][ni][2] + bv0, acc[mi][ni][3] + bv1);
        }
    }
}

// ---------------------------------------------------------------------------
// Flash attention (causal, fp16): 128 queries/block, 8 warps x 16 rows.
// Double-buffered K/V, warp-local P, per-warp masked-tile skip.
// grid (16 reversed, 32), 256 threads, occupancy 2.
// smem halves: K 2x4608 | V 2x4608 | P/Q 9216  = 27648 (55296 B)
// ---------------------------------------------------------------------------
#define AT_ST 72
#define AK_W (64 * AT_ST)               // 4608 halves
#define AV_W (64 * AT_ST)               // 4608 halves
#define AP_OFF (2 * AK_W + 2 * AV_W)    // 18432 halves
#define AP_W  (128 * AT_ST)             // 9216 halves
#define ATT_SMEM ((AP_OFF + AP_W) * 2)  // 55296 bytes

__global__ __launch_bounds__(256, 2) void attn_kernel()
{
    extern __shared__ __half hsm[];
    __half* sP = hsm + AP_OFF;

    const int qt = 15 - blockIdx.x;
    const int bh = blockIdx.y;
    const int b  = bh >> 4;
    const int h  = bh & 15;
    const int tid  = threadIdx.x;
    const int w    = tid >> 5;
    const int lane = tid & 31;
    const int qr   = lane >> 2;
    const int ql   = lane & 3;

    const __half* Qb = g_q + (size_t)bh * S_ * HD_;
    const __half* Kb = g_k + (size_t)bh * S_ * HD_;
    const __half* Vb = g_v + (size_t)bh * S_ * HD_;

    const uint32_t sk_b = (uint32_t)__cvta_generic_to_shared(hsm);
    const uint32_t sv_b = sk_b + 2 * AK_W * 2;
    const uint32_t sp_b = sk_b + AP_OFF * 2;
    // A-type frag address (Q rows / P rows)
    const uint32_t aoff = ((w * 16 + (lane & 15)) * AT_ST) * 2 + (lane >> 4) * 16;
    // K (B via non-trans): 16 key-rows
    const uint32_t koff = ((lane & 15) * AT_ST) * 2 + (lane >> 4) * 16;
    // V (B via trans): key-row klane, hd col (lane>>4)*8
    const int klane = (lane & 7) + ((lane >> 3) & 1) * 8;
    const uint32_t voff = (klane * AT_ST + (lane >> 4) * 8) * 2;

    // ---- stage Q (pre-scaled) into sP, extract A fragments ----
    #pragma unroll
    for (int i = 0; i < 4; i++) {
        int g = i * 256 + tid;           // 0..1023 CP16
        int row = g >> 3, kg = (g & 7) * 8;
        CP16(sp_b + (row * AT_ST + kg) * 2, &Qb[(size_t)(qt * 128 + row) * HD_ + kg]);
    }
    CPCOMMIT(); CPWAIT(0);
    __syncthreads();

    uint32_t qa[4][4];
    #pragma unroll
    for (int kk = 0; kk < 4; kk++) ldm4(qa[kk], sp_b + aoff + kk * 32);
    __syncthreads();                     // Q frags extracted before P reuse

    #define ATT_STAGE(kt, s) {                                                 \
        _Pragma("unroll")                                                      \
        for (int i = 0; i < 4; i++) {                                          \
            int g = i * 256 + tid;       /* 0..1023: 512 K + 512 V CP16 */     \
            int sel = g >> 9; int row = (g >> 3) & 63; int kg = (g & 7) * 8;   \
            uint32_t base = sel ? (sv_b + (s) * AV_W * 2) : (sk_b + (s) * AK_W * 2); \
            const __half* src = sel ? &Vb[(size_t)((kt) * 64 + row) * HD_ + kg] \
                                    : &Kb[(size_t)((kt) * 64 + row) * HD_ + kg]; \
            CP16(base + (row * AT_ST + kg) * 2, src);                          \
        }                                                                      \
    }

    ATT_STAGE(0, 0); CPCOMMIT();

    float O[8][4];
    #pragma unroll
    for (int n = 0; n < 8; n++)
        #pragma unroll
        for (int c = 0; c < 4; c++) O[n][c] = 0.f;
    float m0 = -1e30f, m1 = -1e30f, l0 = 0.f, l1 = 0.f;

    const int rbase = qt * 128 + w * 16;
    const int nkt = 2 * qt + 2;

    for (int kt = 0; kt < nkt; kt++) {
        const int buf = kt & 1;
        CPWAIT(0);
        __syncthreads();
        if (kt + 1 < nkt) { ATT_STAGE(kt + 1, buf ^ 1); }
        CPCOMMIT();

        if (kt * 64 > rbase + 15) continue;   // fully masked for this warp

        // ---- QK^T ----
        const uint32_t kbase = sk_b + buf * AK_W * 2;
        float sc[8][4];
        #pragma unroll
        for (int n = 0; n < 8; n++)
            #pragma unroll
            for (int c = 0; c < 4; c++) sc[n][c] = 0.f;
        #pragma unroll
        for (int kk = 0; kk < 4; kk++) {
            #pragma unroll
            for (int j = 0; j < 4; j++) {
                uint32_t kb[4];
                ldm4(kb, kbase + koff + j * 16 * AT_ST * 2 + kk * 32);
                mma_f16(sc[2 * j],     qa[kk], kb[0], kb[2]);
                mma_f16(sc[2 * j + 1], qa[kk], kb[1], kb[3]);
            }
        }

        if (kt * 64 + 63 > rbase) {      // partial causal mask
            const int r0 = rbase + qr;
            const int c0 = kt * 64;
            #pragma unroll
            for (int n = 0; n < 8; n++) {
                int cg = c0 + n * 8 + 2 * ql;
                if (cg     > r0)     sc[n][0] = -1e30f;
                if (cg + 1 > r0)     sc[n][1] = -1e30f;
                if (cg     > r0 + 8) sc[n][2] = -1e30f;
                if (cg + 1 > r0 + 8) sc[n][3] = -1e30f;
            }
        }

        // ---- online softmax (fp32) ----
        float mt0 = -1e30f, mt1 = -1e30f;
        #pragma unroll
        for (int n = 0; n < 8; n++) {
            mt0 = fmaxf(mt0, fmaxf(sc[n][0], sc[n][1]));
            mt1 = fmaxf(mt1, fmaxf(sc[n][2], sc[n][3]));
        }
        mt0 = fmaxf(mt0, __shfl_xor_sync(0xffffffffu, mt0, 1));
        mt0 = fmaxf(mt0, __shfl_xor_sync(0xffffffffu, mt0, 2));
        mt1 = fmaxf(mt1, __shfl_xor_sync(0xffffffffu, mt1, 1));
        mt1 = fmaxf(mt1, __shfl_xor_sync(0xffffffffu, mt1, 2));
        float mn0 = fmaxf(m0, mt0), mn1 = fmaxf(m1, mt1);
        float cr0 = __expf(m0 - mn0), cr1 = __expf(m1 - mn1);
        m0 = mn0; m1 = mn1;
        #pragma unroll
        for (int n = 0; n < 8; n++) {
            O[n][0] *= cr0; O[n][1] *= cr0;
            O[n][2] *= cr1; O[n][3] *= cr1;
        }
        float s0 = 0.f, s1 = 0.f;
        #pragma unroll
        for (int n = 0; n < 8; n++) {
            sc[n][0] = __expf(sc[n][0] - mn0);
            sc[n][1] = __expf(sc[n][1] - mn0);
            sc[n][2] = __expf(sc[n][2] - mn1);
            sc[n][3] = __expf(sc[n][3] - mn1);
            s0 += sc[n][0] + sc[n][1];
            s1 += sc[n][2] + sc[n][3];
        }
        s0 += __shfl_xor_sync(0xffffffffu, s0, 1);
        s0 += __shfl_xor_sync(0xffffffffu, s0, 2);
        s1 += __shfl_xor_sync(0xffffffffu, s1, 1);
        s1 += __shfl_xor_sync(0xffffffffu, s1, 2);
        l0 = l0 * cr0 + s0;
        l1 = l1 * cr1 + s1;

        // ---- P (fp16, warp-local rows only) ----
        #pragma unroll
        for (int n = 0; n < 8; n++) {
            int cc = n * 8 + 2 * ql;
            *(__half2*)&sP[(w * 16 + qr) * AT_ST + cc] =
                __floats2half2_rn(sc[n][0], sc[n][1]);
            *(__half2*)&sP[(w * 16 + qr + 8) * AT_ST + cc] =
                __floats2half2_rn(sc[n][2], sc[n][3]);
        }
        __syncwarp();

        // ---- P @ V ----
        const uint32_t vbase = sv_b + buf * AV_W * 2;
        #pragma unroll
        for (int kk = 0; kk < 4; kk++) {
            uint32_t pa[4];
            ldm4(pa, sp_b + aoff + kk * 32);
            #pragma unroll
            for (int j = 0; j < 4; j++) {
                uint32_t vb[4];
                ldm4t(vb, vbase + voff + (kk * 16 * AT_ST + j * 16) * 2);
                mma_f16(O[2 * j],     pa, vb[0], vb[1]);
                mma_f16(O[2 * j + 1], pa, vb[2], vb[3]);
            }
        }
    }

    // ---- normalize + store fp16 to g_wv [B,S,H*HD] ----
    float inv0 = 1.f / l0, inv1 = 1.f / l1;
    int r0g = qt * 128 + w * 16 + qr;
    __half* base0 = g_wv + ((size_t)b * S_ + r0g) * D_ + h * HD_;
    __half* base1 = g_wv + ((size_t)b * S_ + r0g + 8) * D_ + h * HD_;
    #pragma unroll
    for (int n = 0; n < 8; n++) {
        int cc = n * 8 + 2 * ql;
        *(__half2*)&base0[cc] = __floats2half2_rn(O[n][0] * inv0, O[n][1] * inv0);
        *(__half2*)&base1[cc] = __floats2half2_rn(O[n][2] * inv1, O[n][3] * inv1);
    }
}

// ---------------------------------------------------------------------------
// Output projection (fp16): 512 threads, tile 128x256x32, 3-buffer ring.
// A [row][k] and B [n][k] both stride 40 halves, non-trans ldmatrix.
// grid (32, 4) = 128 blocks.
// ---------------------------------------------------------------------------
#define OA_ST 40
#define OAW   (128 * OA_ST)      // 5120 halves
#define OBW   (256 * OA_ST)      // 10240 halves
#define OSTG  (OAW + OBW)        // 15360 halves/stage
#define OP_SMEM (3 * OSTG * 2)   // 92160 bytes

__global__ __launch_bounds__(512, 1) void oproj_kernel(
    const float* __restrict__ bo, float* __restrict__ out)
{
    extern __shared__ __half hsm[];
    const int rt = blockIdx.x, ct = blockIdx.y;

    const int tid  = threadIdx.x;
    const int wid  = tid >> 5;
    const int lane = tid & 31;
    const int wm   = wid >> 2, wn = wid & 3;
    const int ql   = lane & 3, qr = lane >> 2;
    const int row0 = rt * 128;
    const int col0 = ct * 256;

    const uint32_t sm0 = (uint32_t)__cvta_generic_to_shared(hsm);
    const uint32_t aLane = ((wm * 32 + (lane & 15)) * OA_ST) * 2 + (lane >> 4) * 16;
    const uint32_t bLane = ((wn * 64 + (lane & 15)) * OA_ST) * 2 + (lane >> 4) * 16;

    float acc[2][8][4];
    #pragma unroll
    for (int mi = 0; mi < 2; mi++)
        #pragma unroll
        for (int ni = 0; ni < 8; ni++)
            #pragma unroll
            for (int c = 0; c < 4; c++) acc[mi][ni][c] = 0.f;

    #define OP_STAGE(c, s) {                                                   \
        uint32_t sb = sm0 + (s) * OSTG * 2;                                    \
        {   int g = tid; int row = g >> 2; int kg = (g & 3) * 8;               \
            CP16(sb + (row * OA_ST + kg) * 2,                                  \
                 &g_wv[(size_t)(row0 + row) * D_ + (c) * 32 + kg]);            \
        }                                                                      \
        _Pragma("unroll")                                                      \
        for (int i = 0; i < 2; i++) {                                          \
            int g = i * 512 + tid; int n = g >> 2; int kg = (g & 3) * 8;       \
            CP16(sb + (OAW + n * OA_ST + kg) * 2,                              \
                 &g_woh[(size_t)(col0 + n) * D_ + (c) * 32 + kg]);             \
        }                                                                      \
    }

    OP_STAGE(0, 0); CPCOMMIT();
    OP_STAGE(1, 1); CPCOMMIT();

    for (int c = 0; c < 32; c++) {
        const int cur = c % 3;
        CPWAIT(1);
        __syncthreads();
        if (c + 2 < 32) { OP_STAGE(c + 2, (c + 2) % 3); }
        CPCOMMIT();

        const uint32_t sAb = sm0 + cur * OSTG * 2;
        const uint32_t sBb = sAb + OAW * 2;

        #pragma unroll
        for (int kk = 0; kk < 2; kk++) {
            uint32_t a[2][4];
            #pragma unroll
            for (int mi = 0; mi < 2; mi++)
                ldm4(a[mi], sAb + aLane + mi * 16 * OA_ST * 2 + kk * 32);
            uint32_t bb[4][4];
            #pragma unroll
            for (int nj = 0; nj < 4; nj++)
                ldm4(bb[nj], sBb + bLane + nj * 16 * OA_ST * 2 + kk * 32);
            #pragma unroll
            for (int mi = 0; mi < 2; mi++)
                #pragma unroll
                for (int nj = 0; nj < 4; nj++) {
                    mma_f16(acc[mi][2 * nj],     a[mi], bb[nj][0], bb[nj][2]);
                    mma_f16(acc[mi][2 * nj + 1], a[mi], bb[nj][1], bb[nj][3]);
                }
        }
    }

    #pragma unroll
    for (int mi = 0; mi < 2; mi++) {
        int row = row0 + wm * 32 + mi * 16 + qr;
        #pragma unroll
        for (int ni = 0; ni < 8; ni++) {
            int col = col0 + wn * 64 + ni * 8 + 2 * ql;
            float bv0 = bo[col], bv1 = bo[col + 1];
            *(float2*)&out[(size_t)row * D_ + col] =
                make_float2(acc[mi][ni][0] + bv0, acc[mi][ni][1] + bv1);
            *(float2*)&out[(size_t)(row + 8) * D_ + col] =
                make_float2(acc[mi][ni][2] + bv0, acc[mi][ni][3] + bv1);
        }
    }
}

// ---------------------------------------------------------------------------
// Launch. metadata order: x, Wq, bq, Wk, bk, Wv, bv, Wo, bo
// ---------------------------------------------------------------------------
extern "C" void kernel_launch(void* const* d_in, const int* in_sizes, int n_in,
                              void* d_out, int out_size)
{
    const float* x  = (const float*)d_in[0];
    const float* Wq = (const float*)d_in[1];
    const float* bq = (const float*)d_in[2];
    const float* Wk = (const float*)d_in[3];
    const float* bk = (const float*)d_in[4];
    const float* Wv = (const float*)d_in[5];
    const float* bv = (const float*)d_in[6];
    const float* Wo = (const float*)d_in[7];
    const float* bo = (const float*)d_in[8];
    float* out = (float*)d_out;

    cudaFuncSetAttribute(qkv_kernel,   cudaFuncAttributeMaxDynamicSharedMemorySize, QKV_SMEM);
    cudaFuncSetAttribute(attn_kernel,  cudaFuncAttributeMaxDynamicSharedMemorySize, ATT_SMEM);
    cudaFuncSetAttribute(oproj_kernel, cudaFuncAttributeMaxDynamicSharedMemorySize, OP_SMEM);

    const long long ntot = (long long)NX + 4LL * NW + H_ * HD_;
    convert_kernel<<<(int)((ntot + 255) / 256), 256>>>(x, Wq, bq, Wk, Wv, Wo);

    dim3 g1(BS_ / 128, H_ / 4, 3);
    qkv_kernel<<<g1, 512, QKV_SMEM>>>(bk, bv);

    dim3 g2(S_ / 128, B_ * H_);
    attn_kernel<<<g2, 256, ATT_SMEM>>>();

    dim3 g3(BS_ / 128, D_ / 256);
    oproj_kernel<<<g3, 512, OP_SMEM>>>(bo, out);
}